// round 16
// baseline (speedup 1.0000x reference)
#include <cuda_runtime.h>
#include <math.h>

#define B 32
#define NTOK 4096
#define C 768
#define H 12
#define CH 16           // outer chunks per batch (256 tokens each)
#define SUBS 8          // sub-chunks per CTA
#define TPC 32          // tokens per sub-chunk tile
#define XSTR 772        // xs row stride in floats (768 + 4 pad)

typedef unsigned long long u64;

// ---------------- scratch ----------------
__device__ __align__(16) float g_q[B * C];
__device__ __align__(16) float g_t[B * C * H];
__device__ __align__(16) float g_cl[B * CH * H];
__device__ __align__(16) float g_yp[CH * B * H * C];
__device__ __align__(16) float g_cls[B * C];

// ---------------- f32x2 helpers ----------------
#define FMA2(d, a, b) asm("fma.rn.f32x2 %0, %1, %2, %0;" : "+l"(d) : "l"(a), "l"(b))
#define ADD2(d, a)    asm("add.rn.f32x2 %0, %0, %1;"     : "+l"(d) : "l"(a))

__device__ __forceinline__ u64 dup2(float v) {
    u64 r;
    asm("mov.b64 %0, {%1, %1};" : "=l"(r) : "r"(__float_as_uint(v)));
    return r;
}
__device__ __forceinline__ float2 unpk(u64 p) {
    float2 r;
    r.x = __uint_as_float((unsigned int)p);
    r.y = __uint_as_float((unsigned int)(p >> 32));
    return r;
}

// smem map (bytes) — identical to R15 k_fused:
#define OFF_T2S   98816
#define OFF_W2S   111104
#define OFF_REDL  114176
#define FUSED_SMEM 114304

// ---------------- K0a: q — 2 batches per CTA, grid (12, 16) ----------------
__global__ void k_q_kern(const float* __restrict__ x, const float* __restrict__ Wq) {
    int jj = blockIdx.x, bg = blockIdx.y, tid = threadIdx.x;
    __shared__ float xs0[C], xs1[C];
    __shared__ float red0[256], red1[256];
    const float* xr0 = x + (size_t)(bg * 2 + 0) * NTOK * C;
    const float* xr1 = x + (size_t)(bg * 2 + 1) * NTOK * C;
    for (int i = tid; i < C; i += 256) { xs0[i] = xr0[i]; xs1[i] = xr1[i]; }
    __syncthreads();
    int col = jj * 64 + (tid & 63), q = tid >> 6;
    float a0 = 0.f, a1 = 0.f;
    const float* wcol = Wq + (size_t)(q * 192) * C + col;
    #pragma unroll 8
    for (int c = 0; c < 192; c++) {
        float w = wcol[(size_t)c * C];
        a0 = fmaf(xs0[q * 192 + c], w, a0);
        a1 = fmaf(xs1[q * 192 + c], w, a1);
    }
    red0[tid] = a0;
    red1[tid] = a1;
    __syncthreads();
    if (tid < 64)
        g_q[(size_t)(bg * 2) * C + jj * 64 + tid] =
            (red0[tid] + red0[tid + 64] + red0[tid + 128] + red0[tid + 192]) * 0.125f;
    else if (tid < 128) {
        int d = tid - 64;
        g_q[(size_t)(bg * 2 + 1) * C + jj * 64 + d] =
            (red1[d] + red1[d + 64] + red1[d + 128] + red1[d + 192]) * 0.125f;
    }
}

// ---------------- K0b: t — 2 batches per CTA, grid (32, 16), 288 thr ----------------
#define TROWS 12
__global__ void k_t_kern(const float* __restrict__ Wkv, int cbase) {
    __shared__ float wk[TROWS * C];
    __shared__ float qs[2 * C];
    int bg = blockIdx.y, c0 = (blockIdx.x + cbase) * TROWS, tid = threadIdx.x;  // 288 thr
    for (int i = tid; i < 2 * C; i += 288)
        qs[i] = g_q[(size_t)(bg * 2 + i / C) * C + (i % C)];
    for (int i = tid; i < TROWS * C; i += 288)
        wk[i] = Wkv[(size_t)(c0 + i / C) * (2 * C) + (i % C)];
    __syncthreads();
    int h = tid % 12, bl = (tid / 12) & 1, cl = tid / 24;
    const float* qrow = &qs[bl * C];
    float a0 = 0.f, a1 = 0.f, a2 = 0.f, a3 = 0.f;
    #pragma unroll
    for (int j = 0; j < 16; j++) {
        int d4 = ((j + h) & 15) * 4;
        float4 w = *(const float4*)&wk[cl * C + h * 64 + d4];
        float4 q4 = *(const float4*)&qrow[h * 64 + d4];
        a0 = fmaf(w.x, q4.x, a0); a1 = fmaf(w.y, q4.y, a1);
        a2 = fmaf(w.z, q4.z, a2); a3 = fmaf(w.w, q4.w, a3);
    }
    g_t[(size_t)(bg * 2 + bl) * C * H + (size_t)(c0 + cl) * H + h] = (a0 + a1) + (a2 + a3);
}

// ---------------- K1 fused (UNCHANGED from R15) ----------------
__global__ void __launch_bounds__(256, 2) k_fused(const float* __restrict__ x) {
    extern __shared__ __align__(16) char dyn[];
    float* xs = (float*)dyn;
    u64* t2s = (u64*)(dyn + OFF_T2S);
    u64* w2s = (u64*)(dyn + OFF_W2S);
    float* redl = (float*)(dyn + OFF_REDL);

    int b = blockIdx.y, ch = blockIdx.x, tid = threadIdx.x;
    int wid = tid >> 5, lane = tid & 31;
    int pp = tid >> 4, np = tid & 15;
    int g = tid >> 7, ct = tid & 127;
    const float* tb = g_t + (size_t)b * C * H;
    const u64* tsrc = (const u64*)tb;
    const float* xbase = x + ((size_t)b * NTOK + (size_t)ch * 256) * C;

    unsigned sxs = (unsigned)__cvta_generic_to_shared(xs);
    unsigned st2 = (unsigned)__cvta_generic_to_shared(t2s);

    #define STAGE_T0()                                                          \
        {                                                                       \
            unsigned d0 = st2 + tid * 8;                                        \
            asm volatile("cp.async.ca.shared.global [%0], [%1], 8;\n" ::        \
                         "r"(d0), "l"(tsrc + tid) : "memory");                  \
            asm volatile("cp.async.ca.shared.global [%0], [%1], 8;\n" ::        \
                         "r"(d0 + 2048), "l"(tsrc + 256 + tid) : "memory");     \
            asm volatile("cp.async.ca.shared.global [%0], [%1], 8;\n" ::        \
                         "r"(d0 + 4096), "l"(tsrc + 512 + tid) : "memory");     \
            asm volatile("cp.async.commit_group;\n" ::: "memory");              \
        }

    u64 ya[6][3];
    #pragma unroll
    for (int hh = 0; hh < 6; hh++) {
        #pragma unroll
        for (int pc = 0; pc < 3; pc++) ya[hh][pc] = 0ull;
    }
    float lacc[4] = {0.f, 0.f, 0.f, 0.f};

    #pragma unroll
    for (int j = 0; j < 24; j++) {
        int f = tid * 4 + j * 1024;
        int n = f / 768;
        asm volatile("cp.async.cg.shared.global [%0], [%1], 16;\n" ::
                     "r"(sxs + (unsigned)(f * 4 + n * 16)), "l"(xbase + f) : "memory");
    }
    asm volatile("cp.async.commit_group;\n" ::: "memory");
    STAGE_T0();

    #pragma unroll 1
    for (int s = 0; s < SUBS; s++) {
        u64 acc0[6], acc1[6];
        #pragma unroll
        for (int i = 0; i < 6; i++) { acc0[i] = 0ull; acc1[i] = 0ull; }

        #pragma unroll
        for (int r = 0; r < 6; r++) {
            asm volatile("cp.async.wait_group 0;\n" ::: "memory");
            __syncthreads();
            if (r < 5) {
                unsigned d = st2 + (unsigned)(((r + 1) & 1) * 6144) + tid * 8;
                const u64* srcr = tsrc + (r + 1) * 768;
                asm volatile("cp.async.ca.shared.global [%0], [%1], 8;\n" ::
                             "r"(d), "l"(srcr + tid) : "memory");
                asm volatile("cp.async.ca.shared.global [%0], [%1], 8;\n" ::
                             "r"(d + 2048), "l"(srcr + 256 + tid) : "memory");
                asm volatile("cp.async.ca.shared.global [%0], [%1], 8;\n" ::
                             "r"(d + 4096), "l"(srcr + 512 + tid) : "memory");
                asm volatile("cp.async.commit_group;\n" ::: "memory");
            }

            const u64* tbuf = t2s + (r & 1) * 768;
            int cb = r * 128 + pp * 8;
            float xa0[8], xa1[8];
            *(float4*)&xa0[0] = *(const float4*)&xs[np * XSTR + cb];
            *(float4*)&xa0[4] = *(const float4*)&xs[np * XSTR + cb + 4];
            *(float4*)&xa1[0] = *(const float4*)&xs[(np + 16) * XSTR + cb];
            *(float4*)&xa1[4] = *(const float4*)&xs[(np + 16) * XSTR + cb + 4];
            #pragma unroll
            for (int e = 0; e < 8; e++) {
                const u64* tp = &tbuf[(pp * 8 + e) * 6];
                ulonglong2 ta = *(const ulonglong2*)&tp[0];
                ulonglong2 tb2 = *(const ulonglong2*)&tp[2];
                ulonglong2 tc = *(const ulonglong2*)&tp[4];
                u64 d0 = dup2(xa0[e]);
                u64 d1 = dup2(xa1[e]);
                FMA2(acc0[0], d0, ta.x);  FMA2(acc0[1], d0, ta.y);
                FMA2(acc0[2], d0, tb2.x); FMA2(acc0[3], d0, tb2.y);
                FMA2(acc0[4], d0, tc.x);  FMA2(acc0[5], d0, tc.y);
                FMA2(acc1[0], d1, ta.x);  FMA2(acc1[1], d1, ta.y);
                FMA2(acc1[2], d1, tb2.x); FMA2(acc1[3], d1, tb2.y);
                FMA2(acc1[4], d1, tc.x);  FMA2(acc1[5], d1, tc.y);
            }
        }
        __syncthreads();

        ulonglong2* redq = (ulonglong2*)t2s;
        redq[tid]       = make_ulonglong2(acc0[0], acc0[1]);
        redq[256 + tid] = make_ulonglong2(acc0[2], acc0[3]);
        redq[512 + tid] = make_ulonglong2(acc0[4], acc0[5]);
        __syncthreads();
        u64 sx = 0ull, sy = 0ull;
        if (wid < 3 && lane < 16) {
            #pragma unroll
            for (int p2 = 0; p2 < 16; p2++) {
                ulonglong2 v = redq[wid * 256 + p2 * 16 + lane];
                ADD2(sx, v.x); ADD2(sy, v.y);
            }
        }
        __syncthreads();
        redq[tid]       = make_ulonglong2(acc1[0], acc1[1]);
        redq[256 + tid] = make_ulonglong2(acc1[2], acc1[3]);
        redq[512 + tid] = make_ulonglong2(acc1[4], acc1[5]);
        __syncthreads();
        if (wid < 3 && lane < 16) {
            float2 a0 = unpk(sx), a1 = unpk(sy);
            float e0 = __expf(a0.x), e1 = __expf(a0.y);
            float e2 = __expf(a1.x), e3 = __expf(a1.y);
            int base = lane * 12 + 4 * wid;
            *(ulonglong2*)&w2s[base]     = make_ulonglong2(dup2(e0), dup2(e1));
            *(ulonglong2*)&w2s[base + 2] = make_ulonglong2(dup2(e2), dup2(e3));
            lacc[0] += e0; lacc[1] += e1; lacc[2] += e2; lacc[3] += e3;
        } else if (wid < 6 && lane < 16) {
            int j2 = wid - 3;
            u64 tx = 0ull, ty = 0ull;
            #pragma unroll
            for (int p2 = 0; p2 < 16; p2++) {
                ulonglong2 v = redq[j2 * 256 + p2 * 16 + lane];
                ADD2(tx, v.x); ADD2(ty, v.y);
            }
            float2 a0 = unpk(tx), a1 = unpk(ty);
            float e0 = __expf(a0.x), e1 = __expf(a0.y);
            float e2 = __expf(a1.x), e3 = __expf(a1.y);
            int base = (lane + 16) * 12 + 4 * j2;
            *(ulonglong2*)&w2s[base]     = make_ulonglong2(dup2(e0), dup2(e1));
            *(ulonglong2*)&w2s[base + 2] = make_ulonglong2(dup2(e2), dup2(e3));
            lacc[0] += e0; lacc[1] += e1; lacc[2] += e2; lacc[3] += e3;
        }
        __syncthreads();

        const u64* wbase = w2s + g * 6;
        const float* xnext = xbase + (size_t)((s + 1) * TPC) * C;
        int stage_next = (s < SUBS - 1);

        #pragma unroll
        for (int grp = 0; grp < 4; grp++) {
            #pragma unroll
            for (int nn = 0; nn < 8; nn++) {
                int n = grp * 8 + nn;
                ulonglong2 A = *(const ulonglong2*)&xs[n * XSTR + 4 * ct];
                u64 Bv = *(const u64*)&xs[n * XSTR + 512 + 2 * ct];
                const u64* wr = wbase + n * 12;
                ulonglong2 w01 = *(const ulonglong2*)&wr[0];
                ulonglong2 w23 = *(const ulonglong2*)&wr[2];
                ulonglong2 w45 = *(const ulonglong2*)&wr[4];
                FMA2(ya[0][0], A.x, w01.x); FMA2(ya[0][1], A.y, w01.x); FMA2(ya[0][2], Bv, w01.x);
                FMA2(ya[1][0], A.x, w01.y); FMA2(ya[1][1], A.y, w01.y); FMA2(ya[1][2], Bv, w01.y);
                FMA2(ya[2][0], A.x, w23.x); FMA2(ya[2][1], A.y, w23.x); FMA2(ya[2][2], Bv, w23.x);
                FMA2(ya[3][0], A.x, w23.y); FMA2(ya[3][1], A.y, w23.y); FMA2(ya[3][2], Bv, w23.y);
                FMA2(ya[4][0], A.x, w45.x); FMA2(ya[4][1], A.y, w45.x); FMA2(ya[4][2], Bv, w45.x);
                FMA2(ya[5][0], A.x, w45.y); FMA2(ya[5][1], A.y, w45.y); FMA2(ya[5][2], Bv, w45.y);
            }
            if (stage_next) {
                __syncthreads();
                #pragma unroll
                for (int j = 0; j < 6; j++) {
                    int f = grp * 6144 + tid * 4 + j * 1024;
                    int n2 = f / 768;
                    asm volatile("cp.async.cg.shared.global [%0], [%1], 16;\n" ::
                                 "r"(sxs + (unsigned)(f * 4 + n2 * 16)), "l"(xnext + f) : "memory");
                }
                asm volatile("cp.async.commit_group;\n" ::: "memory");
            }
        }
        if (stage_next) STAGE_T0();
    }
    #undef STAGE_T0

    u64* ypu = (u64*)(g_yp + (((size_t)ch * B + b) * H + g * 6) * C);
    #pragma unroll
    for (int hh = 0; hh < 6; hh++) {
        *(ulonglong2*)(ypu + (size_t)hh * 384 + 2 * ct) = make_ulonglong2(ya[hh][0], ya[hh][1]);
        ypu[(size_t)hh * 384 + 256 + ct] = ya[hh][2];
    }

    #pragma unroll
    for (int i = 0; i < 4; i++) {
        #pragma unroll
        for (int o = 16; o; o >>= 1)
            lacc[i] += __shfl_xor_sync(0xffffffffu, lacc[i], o);
    }
    if (wid >= 3 && wid < 6 && lane == 0) {
        #pragma unroll
        for (int i = 0; i < 4; i++) redl[(wid - 3) * 4 + i] = lacc[i];
    }
    __syncthreads();
    if (wid < 3 && lane == 0) {
        #pragma unroll
        for (int i = 0; i < 4; i++)
            g_cl[((size_t)b * CH + ch) * H + 4 * wid + i] = lacc[i] + redl[wid * 4 + i];
    }
}

// ---------------- K2: cls — 2 batches per CTA, grid (12, 16) ----------------
__global__ void k_cls(const float* __restrict__ Wkv) {
    int h = blockIdx.x, bg = blockIdx.y, tid = threadIdx.x;
    __shared__ float y_s[2 * C];
    __shared__ float red[256];
    __shared__ float rsc_s[2];

    if (tid < 2) {
        int b = bg * 2 + tid;
        float L = 0.f;
        #pragma unroll
        for (int ch = 0; ch < CH; ch++) L += g_cl[((size_t)b * CH + ch) * H + h];
        rsc_s[tid] = 1.f / L;
    }
    __syncthreads();

    for (int i = tid; i < 2 * C; i += 256) {
        int bl = i / C, c = i - bl * C;
        int b = bg * 2 + bl;
        float s = 0.f;
        #pragma unroll
        for (int ch = 0; ch < CH; ch++)
            s += g_yp[(((size_t)ch * B + b) * H + h) * C + c];
        y_s[i] = s * rsc_s[bl];
    }
    __syncthreads();

    int d = tid & 63, sel = tid >> 6;       // sel: bit0 = batch, bit1 = c-half
    int bl = sel & 1, q2 = sel >> 1;
    float acc = 0.f;
    const float* wcol = Wkv + (size_t)(q2 * 384) * (2 * C) + C + h * 64 + d;
    const float* yrow = &y_s[bl * C + q2 * 384];
    #pragma unroll 8
    for (int c = 0; c < 384; c++)
        acc = fmaf(yrow[c], wcol[(size_t)c * (2 * C)], acc);
    red[tid] = acc;
    __syncthreads();
    if (tid < 128) {
        int dd = tid & 63, bb = tid >> 6;
        g_cls[(size_t)(bg * 2 + bb) * C + h * 64 + dd] =
            red[bb * 64 + dd] + red[128 + bb * 64 + dd];
    }
}

// ---------------- K3: out — 2 batches per CTA, grid (12, 16) ----------------
__global__ void k_out(const float* __restrict__ Wp, const float* __restrict__ bp,
                      float* __restrict__ out) {
    int jj = blockIdx.x, bg = blockIdx.y, tid = threadIdx.x;
    __shared__ float c_s[2 * C];
    __shared__ float red[256];
    for (int i = tid; i < 2 * C; i += 256)
        c_s[i] = g_cls[(size_t)(bg * 2 + i / C) * C + (i % C)];
    __syncthreads();
    int d = tid & 63, sel = tid >> 6;
    int bl = sel & 1, q2 = sel >> 1;
    int col = jj * 64 + d;
    float acc = 0.f;
    const float* wcol = Wp + (size_t)(q2 * 384) * C + col;
    const float* crow = &c_s[bl * C + q2 * 384];
    #pragma unroll 8
    for (int c = 0; c < 384; c++)
        acc = fmaf(crow[c], wcol[(size_t)c * C], acc);
    red[tid] = acc;
    __syncthreads();
    if (tid < 128) {
        int dd = tid & 63, bb = tid >> 6;
        int col2 = jj * 64 + dd;
        out[(size_t)(bg * 2 + bb) * C + col2] =
            red[bb * 64 + dd] + red[128 + bb * 64 + dd] + bp[col2];
    }
}

// ---------------- launcher ----------------
extern "C" void kernel_launch(void* const* d_in, const int* in_sizes, int n_in,
                              void* d_out, int out_size) {
    const float* x   = (const float*)d_in[0];
    const float* Wq  = (const float*)d_in[1];
    const float* Wkv = (const float*)d_in[2];
    const float* Wp  = (const float*)d_in[3];
    const float* bp  = (const float*)d_in[4];
    float* out = (float*)d_out;

    cudaFuncSetAttribute(k_fused, cudaFuncAttributeMaxDynamicSharedMemorySize, FUSED_SMEM);

    k_q_kern<<<dim3(12, 16), 256>>>(x, Wq);            // launch #1
    k_t_kern<<<dim3(32, 16), 288>>>(Wkv, 0);           // launch #2
    k_t_kern<<<dim3(32, 16), 288>>>(Wkv, 32);          // launch #3
    k_fused <<<dim3(CH, B), 256, FUSED_SMEM>>>(x);     // launch #4 -> profiled
    k_cls   <<<dim3(12, 16), 256>>>(Wkv);              // launch #5
    k_out   <<<dim3(12, 16), 256>>>(Wp, bp, out);      // launch #6
}

// round 17
// speedup vs baseline: 1.0746x; 1.0746x over previous
#include <cuda_runtime.h>
#include <math.h>

#define B 32
#define NTOK 4096
#define C 768
#define H 12
#define CH 16           // outer chunks per batch (256 tokens each)
#define SUBS 8          // sub-chunks per CTA
#define TPC 32          // tokens per sub-chunk tile
#define XSTR 772        // xs row stride in floats (768 + 4 pad)

typedef unsigned long long u64;

// ---------------- scratch ----------------
__device__ __align__(16) float g_t[B * C * H];
__device__ __align__(16) float g_cl[B * CH * H];
__device__ __align__(16) float g_yp[CH * B * H * C];
__device__ __align__(16) float g_cls[B * C];

// ---------------- f32x2 helpers ----------------
#define FMA2(d, a, b) asm("fma.rn.f32x2 %0, %1, %2, %0;" : "+l"(d) : "l"(a), "l"(b))
#define ADD2(d, a)    asm("add.rn.f32x2 %0, %0, %1;"     : "+l"(d) : "l"(a))

__device__ __forceinline__ u64 dup2(float v) {
    u64 r;
    asm("mov.b64 %0, {%1, %1};" : "=l"(r) : "r"(__float_as_uint(v)));
    return r;
}
__device__ __forceinline__ float2 unpk(u64 p) {
    float2 r;
    r.x = __uint_as_float((unsigned int)p);
    r.y = __uint_as_float((unsigned int)(p >> 32));
    return r;
}

// smem map (bytes) — identical to R15 k_fused:
#define OFF_T2S   98816
#define OFF_W2S   111104
#define OFF_REDL  114176
#define FUSED_SMEM 114304

// ---------------- K0: fused q+t — grid (H, B) = (12, 32), 256 threads ----------------
// CTA (h, b): q_h[d] = 0.125 * sum_c x[b,0,c] Wq[c, h*64+d]   (d < 64)
//             t[b,c,h] = sum_d Wk[c, h*64+d] * q_h[d]          (c < 768)
__global__ void k_qt(const float* __restrict__ x, const float* __restrict__ Wq,
                     const float* __restrict__ Wkv) {
    int h = blockIdx.x, b = blockIdx.y, tid = threadIdx.x;
    __shared__ float xs[C];
    __shared__ float red[256];
    __shared__ float qh[64];

    const float* xr = x + (size_t)b * NTOK * C;   // token 0 row
    for (int i = tid; i < C; i += 256) xs[i] = xr[i];
    __syncthreads();

    // --- q_h: 64 outputs, 4-way c-split ---
    int d = tid & 63, qs = tid >> 6;
    float acc = 0.f;
    const float* wq = Wq + (size_t)(qs * 192) * C + h * 64 + d;
    #pragma unroll 8
    for (int c = 0; c < 192; c++)
        acc = fmaf(xs[qs * 192 + c], wq[(size_t)c * C], acc);
    red[tid] = acc;
    __syncthreads();
    if (tid < 64)
        qh[tid] = (red[tid] + red[tid + 64] + red[tid + 128] + red[tid + 192]) * 0.125f;
    __syncthreads();

    // --- t[b, c, h]: 3 c-rows per thread ---
    #pragma unroll
    for (int i = 0; i < 3; i++) {
        int c = tid + i * 256;
        const float* wk = Wkv + (size_t)c * (2 * C) + h * 64;   // K half
        float a0 = 0.f, a1 = 0.f, a2 = 0.f, a3 = 0.f;
        #pragma unroll
        for (int j = 0; j < 16; j++) {
            float4 w = *(const float4*)(wk + j * 4);
            float4 q4 = *(const float4*)&qh[j * 4];
            a0 = fmaf(w.x, q4.x, a0); a1 = fmaf(w.y, q4.y, a1);
            a2 = fmaf(w.z, q4.z, a2); a3 = fmaf(w.w, q4.w, a3);
        }
        g_t[(size_t)b * C * H + (size_t)c * H + h] = (a0 + a1) + (a2 + a3);
    }
}

// ---------------- K1 fused (UNCHANGED from R15) ----------------
__global__ void __launch_bounds__(256, 2) k_fused(const float* __restrict__ x) {
    extern __shared__ __align__(16) char dyn[];
    float* xs = (float*)dyn;
    u64* t2s = (u64*)(dyn + OFF_T2S);
    u64* w2s = (u64*)(dyn + OFF_W2S);
    float* redl = (float*)(dyn + OFF_REDL);

    int b = blockIdx.y, ch = blockIdx.x, tid = threadIdx.x;
    int wid = tid >> 5, lane = tid & 31;
    int pp = tid >> 4, np = tid & 15;
    int g = tid >> 7, ct = tid & 127;
    const float* tb = g_t + (size_t)b * C * H;
    const u64* tsrc = (const u64*)tb;
    const float* xbase = x + ((size_t)b * NTOK + (size_t)ch * 256) * C;

    unsigned sxs = (unsigned)__cvta_generic_to_shared(xs);
    unsigned st2 = (unsigned)__cvta_generic_to_shared(t2s);

    #define STAGE_T0()                                                          \
        {                                                                       \
            unsigned d0 = st2 + tid * 8;                                        \
            asm volatile("cp.async.ca.shared.global [%0], [%1], 8;\n" ::        \
                         "r"(d0), "l"(tsrc + tid) : "memory");                  \
            asm volatile("cp.async.ca.shared.global [%0], [%1], 8;\n" ::        \
                         "r"(d0 + 2048), "l"(tsrc + 256 + tid) : "memory");     \
            asm volatile("cp.async.ca.shared.global [%0], [%1], 8;\n" ::        \
                         "r"(d0 + 4096), "l"(tsrc + 512 + tid) : "memory");     \
            asm volatile("cp.async.commit_group;\n" ::: "memory");              \
        }

    u64 ya[6][3];
    #pragma unroll
    for (int hh = 0; hh < 6; hh++) {
        #pragma unroll
        for (int pc = 0; pc < 3; pc++) ya[hh][pc] = 0ull;
    }
    float lacc[4] = {0.f, 0.f, 0.f, 0.f};

    #pragma unroll
    for (int j = 0; j < 24; j++) {
        int f = tid * 4 + j * 1024;
        int n = f / 768;
        asm volatile("cp.async.cg.shared.global [%0], [%1], 16;\n" ::
                     "r"(sxs + (unsigned)(f * 4 + n * 16)), "l"(xbase + f) : "memory");
    }
    asm volatile("cp.async.commit_group;\n" ::: "memory");
    STAGE_T0();

    #pragma unroll 1
    for (int s = 0; s < SUBS; s++) {
        u64 acc0[6], acc1[6];
        #pragma unroll
        for (int i = 0; i < 6; i++) { acc0[i] = 0ull; acc1[i] = 0ull; }

        #pragma unroll
        for (int r = 0; r < 6; r++) {
            asm volatile("cp.async.wait_group 0;\n" ::: "memory");
            __syncthreads();
            if (r < 5) {
                unsigned d = st2 + (unsigned)(((r + 1) & 1) * 6144) + tid * 8;
                const u64* srcr = tsrc + (r + 1) * 768;
                asm volatile("cp.async.ca.shared.global [%0], [%1], 8;\n" ::
                             "r"(d), "l"(srcr + tid) : "memory");
                asm volatile("cp.async.ca.shared.global [%0], [%1], 8;\n" ::
                             "r"(d + 2048), "l"(srcr + 256 + tid) : "memory");
                asm volatile("cp.async.ca.shared.global [%0], [%1], 8;\n" ::
                             "r"(d + 4096), "l"(srcr + 512 + tid) : "memory");
                asm volatile("cp.async.commit_group;\n" ::: "memory");
            }

            const u64* tbuf = t2s + (r & 1) * 768;
            int cb = r * 128 + pp * 8;
            float xa0[8], xa1[8];
            *(float4*)&xa0[0] = *(const float4*)&xs[np * XSTR + cb];
            *(float4*)&xa0[4] = *(const float4*)&xs[np * XSTR + cb + 4];
            *(float4*)&xa1[0] = *(const float4*)&xs[(np + 16) * XSTR + cb];
            *(float4*)&xa1[4] = *(const float4*)&xs[(np + 16) * XSTR + cb + 4];
            #pragma unroll
            for (int e = 0; e < 8; e++) {
                const u64* tp = &tbuf[(pp * 8 + e) * 6];
                ulonglong2 ta = *(const ulonglong2*)&tp[0];
                ulonglong2 tb2 = *(const ulonglong2*)&tp[2];
                ulonglong2 tc = *(const ulonglong2*)&tp[4];
                u64 d0 = dup2(xa0[e]);
                u64 d1 = dup2(xa1[e]);
                FMA2(acc0[0], d0, ta.x);  FMA2(acc0[1], d0, ta.y);
                FMA2(acc0[2], d0, tb2.x); FMA2(acc0[3], d0, tb2.y);
                FMA2(acc0[4], d0, tc.x);  FMA2(acc0[5], d0, tc.y);
                FMA2(acc1[0], d1, ta.x);  FMA2(acc1[1], d1, ta.y);
                FMA2(acc1[2], d1, tb2.x); FMA2(acc1[3], d1, tb2.y);
                FMA2(acc1[4], d1, tc.x);  FMA2(acc1[5], d1, tc.y);
            }
        }
        __syncthreads();

        ulonglong2* redq = (ulonglong2*)t2s;
        redq[tid]       = make_ulonglong2(acc0[0], acc0[1]);
        redq[256 + tid] = make_ulonglong2(acc0[2], acc0[3]);
        redq[512 + tid] = make_ulonglong2(acc0[4], acc0[5]);
        __syncthreads();
        u64 sx = 0ull, sy = 0ull;
        if (wid < 3 && lane < 16) {
            #pragma unroll
            for (int p2 = 0; p2 < 16; p2++) {
                ulonglong2 v = redq[wid * 256 + p2 * 16 + lane];
                ADD2(sx, v.x); ADD2(sy, v.y);
            }
        }
        __syncthreads();
        redq[tid]       = make_ulonglong2(acc1[0], acc1[1]);
        redq[256 + tid] = make_ulonglong2(acc1[2], acc1[3]);
        redq[512 + tid] = make_ulonglong2(acc1[4], acc1[5]);
        __syncthreads();
        if (wid < 3 && lane < 16) {
            float2 a0 = unpk(sx), a1 = unpk(sy);
            float e0 = __expf(a0.x), e1 = __expf(a0.y);
            float e2 = __expf(a1.x), e3 = __expf(a1.y);
            int base = lane * 12 + 4 * wid;
            *(ulonglong2*)&w2s[base]     = make_ulonglong2(dup2(e0), dup2(e1));
            *(ulonglong2*)&w2s[base + 2] = make_ulonglong2(dup2(e2), dup2(e3));
            lacc[0] += e0; lacc[1] += e1; lacc[2] += e2; lacc[3] += e3;
        } else if (wid < 6 && lane < 16) {
            int j2 = wid - 3;
            u64 tx = 0ull, ty = 0ull;
            #pragma unroll
            for (int p2 = 0; p2 < 16; p2++) {
                ulonglong2 v = redq[j2 * 256 + p2 * 16 + lane];
                ADD2(tx, v.x); ADD2(ty, v.y);
            }
            float2 a0 = unpk(tx), a1 = unpk(ty);
            float e0 = __expf(a0.x), e1 = __expf(a0.y);
            float e2 = __expf(a1.x), e3 = __expf(a1.y);
            int base = (lane + 16) * 12 + 4 * j2;
            *(ulonglong2*)&w2s[base]     = make_ulonglong2(dup2(e0), dup2(e1));
            *(ulonglong2*)&w2s[base + 2] = make_ulonglong2(dup2(e2), dup2(e3));
            lacc[0] += e0; lacc[1] += e1; lacc[2] += e2; lacc[3] += e3;
        }
        __syncthreads();

        const u64* wbase = w2s + g * 6;
        const float* xnext = xbase + (size_t)((s + 1) * TPC) * C;
        int stage_next = (s < SUBS - 1);

        #pragma unroll
        for (int grp = 0; grp < 4; grp++) {
            #pragma unroll
            for (int nn = 0; nn < 8; nn++) {
                int n = grp * 8 + nn;
                ulonglong2 A = *(const ulonglong2*)&xs[n * XSTR + 4 * ct];
                u64 Bv = *(const u64*)&xs[n * XSTR + 512 + 2 * ct];
                const u64* wr = wbase + n * 12;
                ulonglong2 w01 = *(const ulonglong2*)&wr[0];
                ulonglong2 w23 = *(const ulonglong2*)&wr[2];
                ulonglong2 w45 = *(const ulonglong2*)&wr[4];
                FMA2(ya[0][0], A.x, w01.x); FMA2(ya[0][1], A.y, w01.x); FMA2(ya[0][2], Bv, w01.x);
                FMA2(ya[1][0], A.x, w01.y); FMA2(ya[1][1], A.y, w01.y); FMA2(ya[1][2], Bv, w01.y);
                FMA2(ya[2][0], A.x, w23.x); FMA2(ya[2][1], A.y, w23.x); FMA2(ya[2][2], Bv, w23.x);
                FMA2(ya[3][0], A.x, w23.y); FMA2(ya[3][1], A.y, w23.y); FMA2(ya[3][2], Bv, w23.y);
                FMA2(ya[4][0], A.x, w45.x); FMA2(ya[4][1], A.y, w45.x); FMA2(ya[4][2], Bv, w45.x);
                FMA2(ya[5][0], A.x, w45.y); FMA2(ya[5][1], A.y, w45.y); FMA2(ya[5][2], Bv, w45.y);
            }
            if (stage_next) {
                __syncthreads();
                #pragma unroll
                for (int j = 0; j < 6; j++) {
                    int f = grp * 6144 + tid * 4 + j * 1024;
                    int n2 = f / 768;
                    asm volatile("cp.async.cg.shared.global [%0], [%1], 16;\n" ::
                                 "r"(sxs + (unsigned)(f * 4 + n2 * 16)), "l"(xnext + f) : "memory");
                }
                asm volatile("cp.async.commit_group;\n" ::: "memory");
            }
        }
        if (stage_next) STAGE_T0();
    }
    #undef STAGE_T0

    u64* ypu = (u64*)(g_yp + (((size_t)ch * B + b) * H + g * 6) * C);
    #pragma unroll
    for (int hh = 0; hh < 6; hh++) {
        *(ulonglong2*)(ypu + (size_t)hh * 384 + 2 * ct) = make_ulonglong2(ya[hh][0], ya[hh][1]);
        ypu[(size_t)hh * 384 + 256 + ct] = ya[hh][2];
    }

    #pragma unroll
    for (int i = 0; i < 4; i++) {
        #pragma unroll
        for (int o = 16; o; o >>= 1)
            lacc[i] += __shfl_xor_sync(0xffffffffu, lacc[i], o);
    }
    if (wid >= 3 && wid < 6 && lane == 0) {
        #pragma unroll
        for (int i = 0; i < 4; i++) redl[(wid - 3) * 4 + i] = lacc[i];
    }
    __syncthreads();
    if (wid < 3 && lane == 0) {
        #pragma unroll
        for (int i = 0; i < 4; i++)
            g_cl[((size_t)b * CH + ch) * H + 4 * wid + i] = lacc[i] + redl[wid * 4 + i];
    }
}

// ---------------- K2 (R12): cls — one head per CTA, grid (12, B) ----------------
__global__ void k_cls(const float* __restrict__ Wkv) {
    int h = blockIdx.x, b = blockIdx.y, tid = threadIdx.x;
    __shared__ float y_s[C];
    __shared__ float red[256];
    __shared__ float rsc;

    if (tid == 0) {
        float L = 0.f;
        #pragma unroll
        for (int ch = 0; ch < CH; ch++) L += g_cl[((size_t)b * CH + ch) * H + h];
        rsc = 1.f / L;
    }
    __syncthreads();

    float r = rsc;
    for (int i = tid; i < C; i += 256) {
        float s = 0.f;
        #pragma unroll
        for (int ch = 0; ch < CH; ch++)
            s += g_yp[(((size_t)ch * B + b) * H + h) * C + i];
        y_s[i] = s * r;
    }
    __syncthreads();

    int col = h * 64 + (tid & 63), q = tid >> 6;
    float acc = 0.f;
    const float* wcol = Wkv + (size_t)(q * 192) * (2 * C) + C + col;
    #pragma unroll 8
    for (int c = 0; c < 192; c++)
        acc = fmaf(y_s[q * 192 + c], wcol[(size_t)c * (2 * C)], acc);
    red[tid] = acc;
    __syncthreads();
    if (tid < 64)
        g_cls[b * C + h * 64 + tid] =
            red[tid] + red[tid + 64] + red[tid + 128] + red[tid + 192];
}

// ---------------- K3 (R12): out = cls @ Wp + bp — grid (12, B) ----------------
__global__ void k_out(const float* __restrict__ Wp, const float* __restrict__ bp,
                      float* __restrict__ out) {
    int b = blockIdx.y, jj = blockIdx.x, tid = threadIdx.x;
    __shared__ float c_s[C];
    __shared__ float red[256];
    for (int i = tid; i < C; i += 256) c_s[i] = g_cls[b * C + i];
    __syncthreads();
    int col = jj * 64 + (tid & 63), q = tid >> 6;
    float acc = 0.f;
    const float* wcol = Wp + (size_t)(q * 192) * C + col;
    #pragma unroll 8
    for (int c = 0; c < 192; c++)
        acc = fmaf(c_s[q * 192 + c], wcol[(size_t)c * C], acc);
    red[tid] = acc;
    __syncthreads();
    if (tid < 64) {
        int j = jj * 64 + tid;
        out[b * C + j] = red[tid] + red[tid + 64] + red[tid + 128] + red[tid + 192] + bp[j];
    }
}

// ---------------- launcher ----------------
extern "C" void kernel_launch(void* const* d_in, const int* in_sizes, int n_in,
                              void* d_out, int out_size) {
    const float* x   = (const float*)d_in[0];
    const float* Wq  = (const float*)d_in[1];
    const float* Wkv = (const float*)d_in[2];
    const float* Wp  = (const float*)d_in[3];
    const float* bp  = (const float*)d_in[4];
    float* out = (float*)d_out;

    cudaFuncSetAttribute(k_fused, cudaFuncAttributeMaxDynamicSharedMemorySize, FUSED_SMEM);

    k_qt    <<<dim3(12, B), 256>>>(x, Wq, Wkv);        // launch #1 (q+t fused)
    k_fused <<<dim3(CH, B), 256, FUSED_SMEM>>>(x);     // launch #2
    k_cls   <<<dim3(12, B), 256>>>(Wkv);               // launch #3
    k_out   <<<dim3(12, B), 256>>>(Wp, bp, out);       // launch #4 -> profiled
}